// round 15
// baseline (speedup 1.0000x reference)
#include <cuda_runtime.h>
#include <cuda_fp16.h>
#include <cstdint>

#define HW   128
#define CIN  16
#define OOUT 64
#define TILE_H 4
#define XROW 48                 // bytes per pos-row (16ch fp16 padded to 48)
#define SLOT (130 * XROW)       // 6240 B per x row slot
#define NSLOT 5
#define XS_BYTES (NSLOT * SLOT) // 31200

#define SM_XS   0
#define SM_WS   XS_BYTES              // 31200
#define WS_BYTES (9 * 2048)           // 18432
#define SM_BIAS (SM_WS + WS_BYTES)    // 49632
#define SMEM_BYTES (SM_BIAS + 256)    // 49888

// A[i,k] = Re(P_i[r,c]), r=k/4, c=k%4 ; 15 non-identity 2-qubit Paulis.
__constant__ float c_A[15][9] = {
  {0,1,0,0,1,0,0,0,0},   {0,0,0,0,0,0,0,0,0},  {1,0,0,0,0,-1,0,0,0},
  {0,0,1,0,0,0,0,1,1},   {0,0,0,1,0,0,1,0,0},  {0,0,0,0,0,0,0,0,0},
  {0,0,1,0,0,0,0,-1,1},  {0,0,0,0,0,0,0,0,0},  {0,0,0,0,0,0,0,0,0},
  {0,0,0,-1,0,0,1,0,0},  {0,0,0,0,0,0,0,0,0},  {1,0,0,0,0,1,0,0,0},
  {0,1,0,0,1,0,0,0,0},   {0,0,0,0,0,0,0,0,0},  {1,0,0,0,0,-1,0,0,0},
};
__constant__ float c_t0[9] = {1,0,0,0,0,1,0,0,0};

// Fragment-linear fp16 weights: g_Wf[tap 9][j2 4][lane 32][8], 2048 B per tap.
__device__ __half g_Wf[9 * 4 * 32 * 8];

__global__ void prep_weights(const float* __restrict__ w) {
  int idx = blockIdx.x * 256 + threadIdx.x;
  if (idx >= 9216) return;
  int e    = idx & 7;
  int lane = (idx >> 3) & 31;
  int j2   = (idx >> 8) & 3;
  int tap  = idx >> 10;
  int j = 2 * j2 + (e >> 2);
  int n = 8 * j + (lane >> 2);
  int k = 2 * (lane & 3) + (e & 1) + ((e & 2) ? 8 : 0);
  float w3 = c_t0[tap];
#pragma unroll
  for (int i = 0; i < 15; i++) w3 += w[(n * CIN + k) * 15 + i] * c_A[i][tap];
  g_Wf[idx] = __float2half(0.25f * w3);
}

__device__ __forceinline__ uint32_t smem_u32(const void* p) {
  uint32_t a;
  asm("{ .reg .u64 t; cvta.to.shared.u64 t, %1; cvt.u32.u64 %0, t; }"
      : "=r"(a) : "l"(p));
  return a;
}
__device__ __forceinline__ void ldsm4(uint32_t* r, uint32_t addr) {
  asm volatile(
      "ldmatrix.sync.aligned.m8n8.x4.shared.b16 {%0,%1,%2,%3}, [%4];"
      : "=r"(r[0]), "=r"(r[1]), "=r"(r[2]), "=r"(r[3]) : "r"(addr));
}
__device__ __forceinline__ void hmma(float* d, const uint32_t* a, uint32_t b0,
                                     uint32_t b1) {
  asm volatile(
      "mma.sync.aligned.m16n8k16.row.col.f32.f16.f16.f32 "
      "{%0,%1,%2,%3}, {%4,%5,%6,%7}, {%8,%9}, {%0,%1,%2,%3};"
      : "+f"(d[0]), "+f"(d[1]), "+f"(d[2]), "+f"(d[3])
      : "r"(a[0]), "r"(a[1]), "r"(a[2]), "r"(a[3]), "r"(b0), "r"(b1));
}

// Stage input row q into ring slot (q+1)%NSLOT.
// Register transpose: each thread = (pos, 8-channel half); 8 coalesced LDG.32,
// convert, ONE STS.128 (48B-stride, conflict-free).
__device__ __forceinline__ void stage_row(const float* __restrict__ xb,
                                          char* smem, int h0, int q, int tid) {
  const int hs = h0 + q;
  const int slot = (q + 1) % NSLOT;
  const bool hok = (unsigned)hs < (unsigned)HW;
#pragma unroll
  for (int i = tid; i < 2 * 130; i += 128) {
    const int c8 = i / 130, pos = i - c8 * 130;
    const bool ok = hok && pos >= 1 && pos <= 128;
    const float* src =
        xb + ((size_t)(c8 * 8) * HW + hs) * HW + pos - 1;
    __half hv[8];
#pragma unroll
    for (int k = 0; k < 8; k++)
      hv[k] = __float2half(ok ? src[(size_t)k * HW * HW] : 0.f);
    *(uint4*)(smem + SM_XS + slot * SLOT + pos * XROW + c8 * 16) =
        *(uint4*)hv;
  }
}

// CTA: 128 threads, 4 warps (one per w-strip mq). Warp tile m32 x n64.
// B fragments fully register-resident (9 taps x 4 uint4 = 144 regs).
// One output row per iteration, TILE_H rows per CTA, 2 CTAs/SM (255 regs).
__global__ void __launch_bounds__(128, 2)
quanv(const float* __restrict__ x, const float* __restrict__ bias,
      float* __restrict__ out) {
  extern __shared__ char smem[];
  const int tid = threadIdx.x;
  const int lane = tid & 31;
  const int mq = tid >> 5;        // w-strip
  const int h0 = blockIdx.x * TILE_H;
  const int b = blockIdx.y;

  // stage fp16 fragment-linear weights (18432 B)
  {
    const float4* s = (const float4*)g_Wf;
    float4* d = (float4*)(smem + SM_WS);
    for (int i = tid; i < WS_BYTES / 16; i += 128) d[i] = s[i];
  }
  if (tid < 64) ((float*)(smem + SM_BIAS))[tid] = bias[tid];

  const float* xb = x + (size_t)b * CIN * HW * HW;
  stage_row(xb, smem, h0, -1, tid);
  stage_row(xb, smem, h0, 0, tid);
  stage_row(xb, smem, h0, 1, tid);
  __syncthreads();

  // hoist ALL B fragments into registers (once per CTA)
  uint4 bw[9][4];
#pragma unroll
  for (int tap = 0; tap < 9; tap++) {
    const uint4* wt = (const uint4*)(smem + SM_WS) + tap * 128 + lane;
    bw[tap][0] = wt[0];
    bw[tap][1] = wt[32];
    bw[tap][2] = wt[64];
    bw[tap][3] = wt[96];
  }

  const uint32_t sb = smem_u32(smem);
  const uint32_t laneoff =
      (mq * 32 + (lane & 15)) * XROW + (lane >> 4) * 16;
  const float* bs = (const float*)(smem + SM_BIAS);
  float* obase = out + (size_t)b * OOUT * HW * HW;

#pragma unroll 1
  for (int hr = 0; hr < TILE_H; hr++) {
    float d[2][8][4];
#pragma unroll
    for (int i = 0; i < 2; i++)
#pragma unroll
      for (int j = 0; j < 8; j++)
#pragma unroll
        for (int r = 0; r < 4; r++) d[i][j][r] = 0.f;

    int sl[3];
#pragma unroll
    for (int dh = 0; dh < 3; dh++) sl[dh] = (hr + dh) % NSLOT;

#pragma unroll
    for (int tap = 0; tap < 9; tap++) {
      const int dh = tap / 3, dw = tap - 3 * dh;
      const uint32_t ah = sb + SM_XS + laneoff + sl[dh] * SLOT + dw * XROW;
      uint32_t a0[4], a1[4];
      ldsm4(a0, ah);
      ldsm4(a1, ah + 16 * XROW);
#pragma unroll
      for (int half = 0; half < 2; half++) {
        const uint4 bb0 = bw[tap][half * 2];
        const uint4 bb1 = bw[tap][half * 2 + 1];
        const int j4 = half * 4;
        hmma(d[0][j4 + 0], a0, bb0.x, bb0.y);
        hmma(d[0][j4 + 1], a0, bb0.z, bb0.w);
        hmma(d[0][j4 + 2], a0, bb1.x, bb1.y);
        hmma(d[0][j4 + 3], a0, bb1.z, bb1.w);
        hmma(d[1][j4 + 0], a1, bb0.x, bb0.y);
        hmma(d[1][j4 + 1], a1, bb0.z, bb0.w);
        hmma(d[1][j4 + 2], a1, bb1.x, bb1.y);
        hmma(d[1][j4 + 3], a1, bb1.z, bb1.w);
      }
    }

    // stage row hr+2 into slot (hr+3)%5 (disjoint from this iter's reads)
    if (hr + 2 <= TILE_H) stage_row(xb, smem, h0, hr + 2, tid);

    // direct store with bias: o = 8j+2(lane&3)+(r&1); m = mq*32+16i+(lane>>2)+8*(r>>1)
    float* ob = obase + (size_t)(h0 + hr) * HW;
#pragma unroll
    for (int j = 0; j < 8; j++) {
      const int o = 8 * j + 2 * (lane & 3);
      const float b0 = bs[o];
      const float b1 = bs[o + 1];
      float* p0 = ob + (size_t)o * HW * HW;
      float* p1 = p0 + (size_t)HW * HW;
#pragma unroll
      for (int i = 0; i < 2; i++) {
        const int m = mq * 32 + 16 * i + (lane >> 2);
        p0[m]     = d[i][j][0] + b0;
        p1[m]     = d[i][j][1] + b1;
        p0[m + 8] = d[i][j][2] + b0;
        p1[m + 8] = d[i][j][3] + b1;
      }
    }
    __syncthreads();
  }
}

extern "C" void kernel_launch(void* const* d_in, const int* in_sizes, int n_in,
                              void* d_out, int out_size) {
  const float* x    = (const float*)d_in[0];  // [32,16,128,128]
  const float* w    = (const float*)d_in[1];  // [64,16,15]
  const float* bias = (const float*)d_in[2];  // [64,1]
  float* out = (float*)d_out;                 // [32,64,128,128]

  cudaFuncSetAttribute(quanv, cudaFuncAttributeMaxDynamicSharedMemorySize,
                       SMEM_BYTES);

  prep_weights<<<(9216 + 255) / 256, 256>>>(w);
  quanv<<<dim3(HW / TILE_H, 32), 128, SMEM_BYTES>>>(x, bias, out);
}

// round 17
// speedup vs baseline: 1.1054x; 1.1054x over previous
#include <cuda_runtime.h>
#include <cuda_fp16.h>
#include <cstdint>

#define HW   128
#define CIN  16
#define OOUT 64
#define TILE_H 4
#define XROW 48                 // bytes per pos-row (16ch fp16 padded to 48)
#define SLOT (130 * XROW)       // 6240 B per x row slot
#define NSLOT 5
#define XS_BYTES (NSLOT * SLOT) // 31200

#define SM_XS   0
#define SM_WS   XS_BYTES              // 31200
#define WS_BYTES (9 * 2048)           // 18432
#define SM_BIAS (SM_WS + WS_BYTES)    // 49632
#define SMEM_BYTES (SM_BIAS + 256)    // 49888

// A[i,k] = Re(P_i[r,c]), r=k/4, c=k%4 ; 15 non-identity 2-qubit Paulis.
__constant__ float c_A[15][9] = {
  {0,1,0,0,1,0,0,0,0},   {0,0,0,0,0,0,0,0,0},  {1,0,0,0,0,-1,0,0,0},
  {0,0,1,0,0,0,0,1,1},   {0,0,0,1,0,0,1,0,0},  {0,0,0,0,0,0,0,0,0},
  {0,0,1,0,0,0,0,-1,1},  {0,0,0,0,0,0,0,0,0},  {0,0,0,0,0,0,0,0,0},
  {0,0,0,-1,0,0,1,0,0},  {0,0,0,0,0,0,0,0,0},  {1,0,0,0,0,1,0,0,0},
  {0,1,0,0,1,0,0,0,0},   {0,0,0,0,0,0,0,0,0},  {1,0,0,0,0,-1,0,0,0},
};
__constant__ float c_t0[9] = {1,0,0,0,0,1,0,0,0};

// Fragment-linear fp16 weights: g_Wf[tap 9][j2 4][lane 32][8], 2048 B per tap.
__device__ __half g_Wf[9 * 4 * 32 * 8];

__global__ void prep_weights(const float* __restrict__ w) {
  int idx = blockIdx.x * 256 + threadIdx.x;
  if (idx >= 9216) return;
  int e    = idx & 7;
  int lane = (idx >> 3) & 31;
  int j2   = (idx >> 8) & 3;
  int tap  = idx >> 10;
  int j = 2 * j2 + (e >> 2);
  int n = 8 * j + (lane >> 2);
  int k = 2 * (lane & 3) + (e & 1) + ((e & 2) ? 8 : 0);
  float w3 = c_t0[tap];
#pragma unroll
  for (int i = 0; i < 15; i++) w3 += w[(n * CIN + k) * 15 + i] * c_A[i][tap];
  g_Wf[idx] = __float2half(0.25f * w3);
}

__device__ __forceinline__ uint32_t smem_u32(const void* p) {
  uint32_t a;
  asm("{ .reg .u64 t; cvta.to.shared.u64 t, %1; cvt.u32.u64 %0, t; }"
      : "=r"(a) : "l"(p));
  return a;
}
__device__ __forceinline__ void ldsm4(uint32_t* r, uint32_t addr) {
  asm volatile(
      "ldmatrix.sync.aligned.m8n8.x4.shared.b16 {%0,%1,%2,%3}, [%4];"
      : "=r"(r[0]), "=r"(r[1]), "=r"(r[2]), "=r"(r[3]) : "r"(addr));
}
__device__ __forceinline__ void hmma(float* d, const uint32_t* a, uint32_t b0,
                                     uint32_t b1) {
  asm volatile(
      "mma.sync.aligned.m16n8k16.row.col.f32.f16.f16.f32 "
      "{%0,%1,%2,%3}, {%4,%5,%6,%7}, {%8,%9}, {%0,%1,%2,%3};"
      : "+f"(d[0]), "+f"(d[1]), "+f"(d[2]), "+f"(d[3])
      : "r"(a[0]), "r"(a[1]), "r"(a[2]), "r"(a[3]), "r"(b0), "r"(b1));
}

// --- split staging: LDG early (into regs), convert+STS late ---
// Row has 2*130 = 260 (c8, pos) items; thread owns i = tid, tid+128, tid+256
// (third live only for tid < 4).
__device__ __forceinline__ void stage_load(const float* __restrict__ xb,
                                           int h0, int q, int tid,
                                           float vr[3][8]) {
  const int hs = h0 + q;
  const bool hok = (unsigned)hs < (unsigned)HW;
#pragma unroll
  for (int t = 0; t < 3; t++) {
    const int i = tid + t * 128;
    if (i < 260) {
      const int c8 = i / 130, pos = i - c8 * 130;
      const bool ok = hok && pos >= 1 && pos <= 128;
      const float* src = xb + ((size_t)(c8 * 8) * HW + hs) * HW + pos - 1;
#pragma unroll
      for (int k = 0; k < 8; k++)
        vr[t][k] = ok ? src[(size_t)k * HW * HW] : 0.f;
    }
  }
}
__device__ __forceinline__ void stage_store(char* smem, int q, int tid,
                                            const float vr[3][8]) {
  const int slot = (q + 1) % NSLOT;
#pragma unroll
  for (int t = 0; t < 3; t++) {
    const int i = tid + t * 128;
    if (i < 260) {
      const int c8 = i / 130, pos = i - c8 * 130;
      __half hv[8];
#pragma unroll
      for (int k = 0; k < 8; k++) hv[k] = __float2half(vr[t][k]);
      *(uint4*)(smem + SM_XS + slot * SLOT + pos * XROW + c8 * 16) =
          *(uint4*)hv;
    }
  }
}
__device__ __forceinline__ void stage_row(const float* __restrict__ xb,
                                          char* smem, int h0, int q, int tid) {
  float vr[3][8];
  stage_load(xb, h0, q, tid, vr);
  stage_store(smem, q, tid, vr);
}

// CTA: 128 threads, 4 warps (one per w-strip mq). Warp tile m32 x n64.
// One output row per iteration; staging LDGs pipelined one row ahead.
__global__ void __launch_bounds__(128, 3)
quanv(const float* __restrict__ x, const float* __restrict__ bias,
      float* __restrict__ out) {
  extern __shared__ char smem[];
  const int tid = threadIdx.x;
  const int lane = tid & 31;
  const int mq = tid >> 5;        // w-strip
  const int h0 = blockIdx.x * TILE_H;
  const int b = blockIdx.y;

  // stage fp16 fragment-linear weights (18432 B)
  {
    const float4* s = (const float4*)g_Wf;
    float4* d = (float4*)(smem + SM_WS);
    for (int i = tid; i < WS_BYTES / 16; i += 128) d[i] = s[i];
  }
  if (tid < 64) ((float*)(smem + SM_BIAS))[tid] = bias[tid];

  const float* xb = x + (size_t)b * CIN * HW * HW;
  stage_row(xb, smem, h0, -1, tid);
  stage_row(xb, smem, h0, 0, tid);
  stage_row(xb, smem, h0, 1, tid);

  // prefetch row 2 into registers (STS'd at end of iteration hr=0)
  float vr[3][8];
  stage_load(xb, h0, 2, tid, vr);
  __syncthreads();

  const uint32_t sb = smem_u32(smem);
  const uint32_t laneoff =
      (mq * 32 + (lane & 15)) * XROW + (lane >> 4) * 16;
  const float* bs = (const float*)(smem + SM_BIAS);
  float* obase = out + (size_t)b * OOUT * HW * HW;

#pragma unroll 1
  for (int hr = 0; hr < TILE_H; hr++) {
    float d[2][8][4];
#pragma unroll
    for (int i = 0; i < 2; i++)
#pragma unroll
      for (int j = 0; j < 8; j++)
#pragma unroll
        for (int r = 0; r < 4; r++) d[i][j][r] = 0.f;

    int sl[3];
#pragma unroll
    for (int dh = 0; dh < 3; dh++) sl[dh] = (hr + dh) % NSLOT;

#pragma unroll
    for (int tap = 0; tap < 9; tap++) {
      const int dh = tap / 3, dw = tap - 3 * dh;
      const uint32_t ah = sb + SM_XS + laneoff + sl[dh] * SLOT + dw * XROW;
      uint32_t a0[4], a1[4];
      ldsm4(a0, ah);
      ldsm4(a1, ah + 16 * XROW);
      const uint4* wt = (const uint4*)(smem + SM_WS) + tap * 128 + lane;
#pragma unroll
      for (int half = 0; half < 2; half++) {
        const uint4 bb0 = wt[half * 64];
        const uint4 bb1 = wt[half * 64 + 32];
        const int j4 = half * 4;
        hmma(d[0][j4 + 0], a0, bb0.x, bb0.y);
        hmma(d[0][j4 + 1], a0, bb0.z, bb0.w);
        hmma(d[0][j4 + 2], a0, bb1.x, bb1.y);
        hmma(d[0][j4 + 3], a0, bb1.z, bb1.w);
        hmma(d[1][j4 + 0], a1, bb0.x, bb0.y);
        hmma(d[1][j4 + 1], a1, bb0.z, bb0.w);
        hmma(d[1][j4 + 2], a1, bb1.x, bb1.y);
        hmma(d[1][j4 + 3], a1, bb1.z, bb1.w);
      }
    }

    // STS row hr+2 (regs loaded one iteration ago), then LDG row hr+3
    if (hr + 2 <= TILE_H) stage_store(smem, hr + 2, tid, vr);
    if (hr + 3 <= TILE_H) stage_load(xb, h0, hr + 3, tid, vr);

    // direct store with bias: o = 8j+2(lane&3)+(r&1); m = mq*32+16i+(lane>>2)+8*(r>>1)
    float* ob = obase + (size_t)(h0 + hr) * HW;
#pragma unroll
    for (int j = 0; j < 8; j++) {
      const int o = 8 * j + 2 * (lane & 3);
      const float b0 = bs[o];
      const float b1 = bs[o + 1];
      float* p0 = ob + (size_t)o * HW * HW;
      float* p1 = p0 + (size_t)HW * HW;
#pragma unroll
      for (int i = 0; i < 2; i++) {
        const int m = mq * 32 + 16 * i + (lane >> 2);
        p0[m]     = d[i][j][0] + b0;
        p1[m]     = d[i][j][1] + b1;
        p0[m + 8] = d[i][j][2] + b0;
        p1[m + 8] = d[i][j][3] + b1;
      }
    }
    __syncthreads();
  }
}

extern "C" void kernel_launch(void* const* d_in, const int* in_sizes, int n_in,
                              void* d_out, int out_size) {
  const float* x    = (const float*)d_in[0];  // [32,16,128,128]
  const float* w    = (const float*)d_in[1];  // [64,16,15]
  const float* bias = (const float*)d_in[2];  // [64,1]
  float* out = (float*)d_out;                 // [32,64,128,128]

  cudaFuncSetAttribute(quanv, cudaFuncAttributeMaxDynamicSharedMemorySize,
                       SMEM_BYTES);

  prep_weights<<<(9216 + 255) / 256, 256>>>(w);
  quanv<<<dim3(HW / TILE_H, 32), 128, SMEM_BYTES>>>(x, bias, out);
}